// round 11
// baseline (speedup 1.0000x reference)
#include <cuda_runtime.h>
#include <cuda_bf16.h>
#include <mma.h>
#include <math.h>
#include <stdint.h>

using namespace nvcuda;

#define Nn 50000
#define Dd 128
#define Tt 4
#define Ee 150000
#define Hh 8
#define E4  (Tt * Ee)
#define TN  (Tt * Nn)
#define NEG_SLOPE 0.2f
#define EPSF 1e-6f
#define SCAN_NB ((TN + 1023) / 1024)

// ---------------- scratch (static device globals; no allocation) ----------------
__device__ float g_h[Nn*Dd];
__device__ float g_k[Nn*Dd];
__device__ float g_q[Nn*Dd];
__device__ float g_v[Nn*Dd];
__device__ float g_tmp[Nn*Dd];
__device__ float g_al[TN*Hh];
__device__ float g_ar[TN*Hh];
__device__ float g_xw[(size_t)Tt*Nn*Dd];
__device__ int   g_deg[TN];
__device__ int   g_off[TN];
__device__ int   g_cur[TN];
__device__ int   g_csr[E4];
__device__ int   g_bsum[SCAN_NB];

// ---------------- generic helpers ----------------
__device__ __forceinline__ float geluf(float x) {
    return 0.5f * x * (1.0f + erff(x * 0.7071067811865476f));
}
__device__ __forceinline__ const int* pick_ei(int t, const int* e0, const int* e1,
                                              const int* e2, const int* e3) {
    return (t == 0) ? e0 : (t == 1) ? e1 : (t == 2) ? e2 : e3;
}
__device__ __forceinline__ float dot4(float4 a, float4 b) {
    return a.x*b.x + a.y*b.y + a.z*b.z + a.w*b.w;
}
__device__ __forceinline__ float4 shfl4(float4 v, int src) {
    float4 r;
    r.x = __shfl_sync(0xffffffffu, v.x, src);
    r.y = __shfl_sync(0xffffffffu, v.y, src);
    r.z = __shfl_sync(0xffffffffu, v.z, src);
    r.w = __shfl_sync(0xffffffffu, v.w, src);
    return r;
}
__device__ __forceinline__ float bf16res(float a) {
    return a - __bfloat162float(__float2bfloat16(a));
}

// ---------------- elementwise ----------------
__global__ void add3k(const float4* __restrict__ a, const float4* __restrict__ b,
                      const float4* __restrict__ c, float4* __restrict__ o, int n4) {
    int i = blockIdx.x*blockDim.x + threadIdx.x;
    if (i < n4) {
        float4 x = a[i], y = b[i], z = c[i];
        o[i] = make_float4(x.x+y.x+z.x, x.y+y.y+z.y, x.z+y.z+z.z, x.w+y.w+z.w);
    }
}
__global__ void zeroint(int* __restrict__ p, int n) {
    int i = blockIdx.x*blockDim.x + threadIdx.x;
    if (i < n) p[i] = 0;
}

// ---------------- CSR build ----------------
__global__ void deg_k(const int* __restrict__ e0, const int* __restrict__ e1,
                      const int* __restrict__ e2, const int* __restrict__ e3,
                      int* __restrict__ deg) {
    int idx = blockIdx.x*blockDim.x + threadIdx.x;
    if (idx >= E4) return;
    int t = idx / Ee, e = idx - t*Ee;
    const int* ei = pick_ei(t, e0, e1, e2, e3);
    atomicAdd(&deg[t*Nn + ei[Ee + e]], 1);
}
__global__ void scan_pre(const int* __restrict__ deg, int* __restrict__ bsum) {
    __shared__ int sh[32];
    int g = blockIdx.x*1024 + threadIdx.x;
    int v = (g < TN) ? deg[g] : 0;
    int lane = threadIdx.x & 31, w = threadIdx.x >> 5;
    #pragma unroll
    for (int o = 16; o > 0; o >>= 1) v += __shfl_xor_sync(~0u, v, o);
    if (lane == 0) sh[w] = v;
    __syncthreads();
    if (w == 0) {
        int s = sh[lane];
        #pragma unroll
        for (int o = 16; o > 0; o >>= 1) s += __shfl_xor_sync(~0u, s, o);
        if (lane == 0) bsum[blockIdx.x] = s;
    }
}
__global__ void scan_mid(int* __restrict__ bsum) {
    __shared__ int ws[8];
    int tid = threadIdx.x;
    int v = (tid < SCAN_NB) ? bsum[tid] : 0;
    int lane = tid & 31, w = tid >> 5;
    int x = v;
    #pragma unroll
    for (int o = 1; o < 32; o <<= 1) { int u = __shfl_up_sync(~0u, x, o); if (lane >= o) x += u; }
    if (lane == 31) ws[w] = x;
    __syncthreads();
    if (w == 0 && lane < 8) {
        int y = ws[lane];
        #pragma unroll
        for (int o = 1; o < 8; o <<= 1) { int u = __shfl_up_sync(0xffu, y, o); if (lane >= o) y += u; }
        ws[lane] = y;
    }
    __syncthreads();
    int excl = x - v + (w > 0 ? ws[w-1] : 0);
    if (tid < SCAN_NB) bsum[tid] = excl;
}
__global__ void scan_post(const int* __restrict__ deg, const int* __restrict__ bsum,
                          int* __restrict__ off, int* __restrict__ cur) {
    __shared__ int ws[32];
    int g = blockIdx.x*1024 + threadIdx.x;
    int v = (g < TN) ? deg[g] : 0;
    int lane = threadIdx.x & 31, w = threadIdx.x >> 5;
    int x = v;
    #pragma unroll
    for (int o = 1; o < 32; o <<= 1) { int u = __shfl_up_sync(~0u, x, o); if (lane >= o) x += u; }
    if (lane == 31) ws[w] = x;
    __syncthreads();
    if (w == 0) {
        int y = ws[lane];
        #pragma unroll
        for (int o = 1; o < 32; o <<= 1) { int u = __shfl_up_sync(~0u, y, o); if (lane >= o) y += u; }
        ws[lane] = y;
    }
    __syncthreads();
    int excl = x - v + (w > 0 ? ws[w-1] : 0) + bsum[blockIdx.x];
    if (g < TN) { off[g] = excl; cur[g] = excl; }
}
__global__ void fill_k(const int* __restrict__ e0, const int* __restrict__ e1,
                       const int* __restrict__ e2, const int* __restrict__ e3,
                       int* __restrict__ cur, int* __restrict__ csr) {
    int idx = blockIdx.x*blockDim.x + threadIdx.x;
    if (idx >= E4) return;
    int t = idx / Ee, e = idx - t*Ee;
    const int* ei = pick_ei(t, e0, e1, e2, e3);
    int src = ei[e], dst = ei[Ee + e];
    int slot = atomicAdd(&cur[t*Nn + dst], 1);
    csr[slot] = src;
}

// ---------------- split-bf16 HMMA GEMM (wmma; baseline PTX, works on sm_103) ----
// C[M x 128] = A[M x 128] @ W[128 x 128]: A_hi*B_hi + A_lo*B_hi + A_hi*B_lo,
// fp32 accumulate. 128x128 block tile, 8 warps, each 32x64 (2x4 wmma tiles).
// MODE 0: +bias (kqv). MODE 1: ALAR head dots, no bias (GAT).
// MODE 2: Wo + HGT-post fused epilogue.
struct GemmArgs {
    const float* A;
    const float* W[4];
    const float* bias[4];
    float* C[4];
    const float* asb; const float* adb; float* al; float* ar;        // MODE 1
    const float* hres; const float* g; const float* skip; float* out; // MODE 2
    int M;
};

#define LDA 48    // bf16 elems per A smem row (32 data + pad)
#define LDB 144   // bf16 elems per B smem row (128 data + pad)
#define LDC 132   // fp32 elems per Cst row

template <int MODE>
__global__ void __launch_bounds__(256)
gemm_wm(GemmArgs args) {
    // smem: Ahi[128][48] Alo[128][48] (bf16), then B area (bf16 hi/lo) reused
    // as fp32 Cst[32][132] for the epilogue.
    __shared__ __align__(32) __nv_bfloat16 Ahi[128][LDA];
    __shared__ __align__(32) __nv_bfloat16 Alo[128][LDA];
    __shared__ __align__(32) unsigned char Braw[2 * 32 * LDB * 2];   // 18432 B
    __nv_bfloat16 (*Bhi)[LDB] = (__nv_bfloat16 (*)[LDB])Braw;
    __nv_bfloat16 (*Blo)[LDB] = (__nv_bfloat16 (*)[LDB])(Braw + 32*LDB*2);
    float (*Cst)[LDC] = (float (*)[LDC])Braw;                         // overlay

    const int t = blockIdx.y;
    const float* Ap = args.A;
    const float* W = args.W[t];
    const float* bias = args.bias[t];
    float* C = args.C[t];
    const int br = blockIdx.x * 128;
    const int tid = threadIdx.x;
    const int wid = tid >> 5;
    const int wm = wid & 3;        // 4 warp-rows of 32
    const int wn = wid >> 2;       // 2 warp-cols of 64
    const int M = args.M;

    wmma::fragment<wmma::accumulator, 16, 16, 16, float> acc[2][4];
    #pragma unroll
    for (int mi = 0; mi < 2; mi++)
        #pragma unroll
        for (int ni = 0; ni < 4; ni++) wmma::fill_fragment(acc[mi][ni], 0.0f);

    for (int kc = 0; kc < 4; kc++) {
        __syncthreads();
        // stage A chunk rows br..+127, k = kc*32..+31 (1024 float4)
        #pragma unroll
        for (int it = 0; it < 4; it++) {
            int i = tid + it*256;
            int r = i >> 3, q = i & 7;
            int gr = br + r;
            float4 x = (gr < M) ? *(const float4*)(Ap + (size_t)gr*Dd + kc*32 + q*4)
                                : make_float4(0,0,0,0);
            int c = q*4;
            float xv[4] = {x.x, x.y, x.z, x.w};
            #pragma unroll
            for (int e = 0; e < 4; e++) {
                __nv_bfloat16 hb = __float2bfloat16(xv[e]);
                Ahi[r][c+e] = hb;
                Alo[r][c+e] = __float2bfloat16(xv[e] - __bfloat162float(hb));
            }
        }
        // stage B chunk k = kc*32..+31, all 128 cols (1024 float4)
        #pragma unroll
        for (int it = 0; it < 4; it++) {
            int i = tid + it*256;
            int r = i >> 5, q = i & 31;
            float4 x = *(const float4*)(W + (size_t)(kc*32 + r)*Dd + q*4);
            int c = q*4;
            float xv[4] = {x.x, x.y, x.z, x.w};
            #pragma unroll
            for (int e = 0; e < 4; e++) {
                __nv_bfloat16 hb = __float2bfloat16(xv[e]);
                Bhi[r][c+e] = hb;
                Blo[r][c+e] = __float2bfloat16(xv[e] - __bfloat162float(hb));
            }
        }
        __syncthreads();
        #pragma unroll
        for (int ks = 0; ks < 2; ks++) {
            wmma::fragment<wmma::matrix_a, 16, 16, 16, __nv_bfloat16, wmma::row_major> afh[2], afl[2];
            wmma::fragment<wmma::matrix_b, 16, 16, 16, __nv_bfloat16, wmma::row_major> bf[4];
            #pragma unroll
            for (int mi = 0; mi < 2; mi++) {
                wmma::load_matrix_sync(afh[mi], &Ahi[wm*32 + mi*16][ks*16], LDA);
                wmma::load_matrix_sync(afl[mi], &Alo[wm*32 + mi*16][ks*16], LDA);
            }
            #pragma unroll
            for (int ni = 0; ni < 4; ni++)
                wmma::load_matrix_sync(bf[ni], &Bhi[ks*16][wn*64 + ni*16], LDB);
            #pragma unroll
            for (int mi = 0; mi < 2; mi++)
                #pragma unroll
                for (int ni = 0; ni < 4; ni++) {
                    wmma::mma_sync(acc[mi][ni], afh[mi], bf[ni], acc[mi][ni]);
                    wmma::mma_sync(acc[mi][ni], afl[mi], bf[ni], acc[mi][ni]);
                }
            #pragma unroll
            for (int ni = 0; ni < 4; ni++)
                wmma::load_matrix_sync(bf[ni], &Blo[ks*16][wn*64 + ni*16], LDB);
            #pragma unroll
            for (int mi = 0; mi < 2; mi++)
                #pragma unroll
                for (int ni = 0; ni < 4; ni++)
                    wmma::mma_sync(acc[mi][ni], afh[mi], bf[ni], acc[mi][ni]);
        }
    }

    // ---------------- epilogue: one 32-row warp-group at a time ----------------
    float beta = 0.f, omb = 0.f;
    if (MODE == 2) {
        beta = 1.f / (1.f + expf(-args.skip[0]));
        omb = 1.f - beta;
    }
    const int er = tid >> 3;            // 0..31 local row
    const int c0 = (tid & 7) * 16;      // 16-col chunk (one head)
    const int head = tid & 7;

    for (int gstep = 0; gstep < 4; gstep++) {
        __syncthreads();
        if (wm == gstep) {
            #pragma unroll
            for (int mi = 0; mi < 2; mi++)
                #pragma unroll
                for (int ni = 0; ni < 4; ni++)
                    wmma::store_matrix_sync(&Cst[mi*16][wn*64 + ni*16], acc[mi][ni],
                                            LDC, wmma::mem_row_major);
        }
        __syncthreads();
        int gr = br + gstep*32 + er;
        bool valid = gr < M;
        float d[16];
        #pragma unroll
        for (int j = 0; j < 16; j++) d[j] = Cst[er][c0 + j];

        if (MODE == 0) {
            if (valid) {
                #pragma unroll
                for (int j4 = 0; j4 < 4; j4++) {
                    float4 o;
                    o.x = d[j4*4+0] + bias[c0 + j4*4+0];
                    o.y = d[j4*4+1] + bias[c0 + j4*4+1];
                    o.z = d[j4*4+2] + bias[c0 + j4*4+2];
                    o.w = d[j4*4+3] + bias[c0 + j4*4+3];
                    *(float4*)(C + (size_t)gr*Dd + c0 + j4*4) = o;
                }
            }
        } else if (MODE == 1) {
            if (valid) {
                float pa = 0.f, pr = 0.f;
                #pragma unroll
                for (int j = 0; j < 16; j++) {
                    pa += d[j] * args.asb[t*Dd + c0 + j];
                    pr += d[j] * args.adb[t*Dd + c0 + j];
                }
                #pragma unroll
                for (int j4 = 0; j4 < 4; j4++) {
                    float4 o;
                    o.x = d[j4*4+0]; o.y = d[j4*4+1]; o.z = d[j4*4+2]; o.w = d[j4*4+3];
                    *(float4*)(C + (size_t)gr*Dd + c0 + j4*4) = o;
                }
                int base = (t*Nn + gr)*Hh + head;
                args.al[base] = pa;
                args.ar[base] = pr;
            }
        } else {
            // MODE 2: out = gelu(h + rmsnorm(beta*(d+bias) + (1-beta)*h, g))
            float u[16], hv[16];
            float ss = 0.f;
            #pragma unroll
            for (int j = 0; j < 16; j++) {
                hv[j] = valid ? args.hres[(size_t)gr*Dd + c0 + j] : 0.f;
                u[j] = beta*(d[j] + bias[c0 + j]) + omb*hv[j];
                ss += u[j]*u[j];
            }
            // 8 threads per row are consecutive lanes → reduce within them
            ss += __shfl_xor_sync(~0u, ss, 1);
            ss += __shfl_xor_sync(~0u, ss, 2);
            ss += __shfl_xor_sync(~0u, ss, 4);
            float inv = rsqrtf(ss * (1.0f/Dd) + EPSF);
            if (valid) {
                #pragma unroll
                for (int j4 = 0; j4 < 4; j4++) {
                    float4 o;
                    #pragma unroll
                    for (int e = 0; e < 4; e++) {
                        int j = j4*4 + e;
                        float r = geluf(hv[j] + args.g[c0+j]*u[j]*inv);
                        if (e == 0) o.x = r; else if (e == 1) o.y = r;
                        else if (e == 2) o.z = r; else o.w = r;
                    }
                    *(float4*)(args.out + (size_t)gr*Dd + c0 + j4*4) = o;
                }
            }
        }
    }
}

// ---------------- GAT gather (round-9 version, unchanged) ----------------
__global__ void gat_gather_b(const int* __restrict__ csr, const int* __restrict__ off,
                             const int* __restrict__ deg, const float* __restrict__ al,
                             const float* __restrict__ ar, const float* __restrict__ xw,
                             const float* __restrict__ b, const float* __restrict__ g,
                             float* __restrict__ h) {
    int n = blockIdx.x;
    int tid = threadIdx.x;
    int t = tid >> 5, lane = tid & 31;
    int hh = lane >> 2;
    __shared__ float smf[4][128];
    __shared__ float sw[4];

    {
        int i = t*Nn + n;
        float arn = ar[(size_t)i*Hh + hh];
        float v = al[(size_t)i*Hh + hh] + arn;
        v = v > 0.f ? v : NEG_SLOPE*v;
        float p = expf(v);
        float s = p;
        float4 x = *(const float4*)(xw + (size_t)i*Dd + lane*4);
        float4 f = make_float4(x.x*p, x.y*p, x.z*p, x.w*p);

        const float* alt = al + (size_t)t*Nn*Hh;
        const float* xwt = xw + (size_t)t*Nn*Dd;
        int st = off[i], dg = deg[i];
        for (int j0 = 0; j0 < dg; j0 += 32) {
            int myS = (j0 + lane < dg) ? csr[st + j0 + lane] : 0;
            int cnt = min(32, dg - j0);
            for (int j = 0; j < cnt; j += 4) {
                int s0 = __shfl_sync(~0u, myS, j);
                int s1 = __shfl_sync(~0u, myS, (j+1) & 31);
                int s2 = __shfl_sync(~0u, myS, (j+2) & 31);
                int s3 = __shfl_sync(~0u, myS, (j+3) & 31);
                float a0 = alt[(size_t)s0*Hh + hh];
                float a1 = alt[(size_t)s1*Hh + hh];
                float a2 = alt[(size_t)s2*Hh + hh];
                float a3 = alt[(size_t)s3*Hh + hh];
                float4 x0 = *(const float4*)(xwt + (size_t)s0*Dd + lane*4);
                float4 x1 = *(const float4*)(xwt + (size_t)s1*Dd + lane*4);
                float4 x2 = *(const float4*)(xwt + (size_t)s2*Dd + lane*4);
                float4 x3 = *(const float4*)(xwt + (size_t)s3*Dd + lane*4);
                float v0 = a0 + arn; v0 = v0 > 0.f ? v0 : NEG_SLOPE*v0;
                float v1 = a1 + arn; v1 = v1 > 0.f ? v1 : NEG_SLOPE*v1;
                float v2 = a2 + arn; v2 = v2 > 0.f ? v2 : NEG_SLOPE*v2;
                float v3 = a3 + arn; v3 = v3 > 0.f ? v3 : NEG_SLOPE*v3;
                float p0 = expf(v0);
                float p1 = (j+1 < cnt) ? expf(v1) : 0.f;
                float p2 = (j+2 < cnt) ? expf(v2) : 0.f;
                float p3 = (j+3 < cnt) ? expf(v3) : 0.f;
                s += p0 + p1 + p2 + p3;
                f.x += x0.x*p0 + x1.x*p1 + x2.x*p2 + x3.x*p3;
                f.y += x0.y*p0 + x1.y*p1 + x2.y*p2 + x3.y*p3;
                f.z += x0.z*p0 + x1.z*p1 + x2.z*p2 + x3.z*p3;
                f.w += x0.w*p0 + x1.w*p1 + x2.w*p2 + x3.w*p3;
            }
        }
        float inv = 1.f / s;
        *(float4*)(&smf[t][lane*4]) = make_float4(f.x*inv, f.y*inv, f.z*inv, f.w*inv);
    }
    __syncthreads();

    int d = tid;
    float a = smf[0][d] + smf[1][d] + smf[2][d] + smf[3][d]
            + b[d] + b[Dd + d] + b[2*Dd + d] + b[3*Dd + d];
    float ss = a*a;
    #pragma unroll
    for (int o = 16; o > 0; o >>= 1) ss += __shfl_xor_sync(0xffffffffu, ss, o);
    if (lane == 0) sw[t] = ss;
    __syncthreads();
    float tot = sw[0] + sw[1] + sw[2] + sw[3];
    float inv2 = rsqrtf(tot * (1.0f/Dd) + EPSF);
    int i = n*Dd + d;
    h[i] = geluf(h[i] + g[d] * a * inv2);
}

// ---------------- HGT gather (round-9 version, unchanged) ----------------
__global__ void hgt_gather_b(const int* __restrict__ csr, const int* __restrict__ off,
                             const int* __restrict__ deg, const float* __restrict__ k,
                             const float* __restrict__ q, const float* __restrict__ v,
                             const float* __restrict__ arel, const float* __restrict__ mrel,
                             const float* __restrict__ prel, float* __restrict__ out) {
    int n = blockIdx.x;
    int tid = threadIdx.x;
    int t = tid >> 5, lane = tid & 31;
    int hh = lane >> 2, qd = lane & 3;
    int qbase = lane & ~3;
    __shared__ float smacc[4][128];
    __shared__ float sms[4][8];

    {
        float4 qv = *(const float4*)(q + (size_t)n*Dd + lane*4);
        const float* A = arel + (size_t)((t*Hh + hh)*16)*16;
        float4 qA = make_float4(0,0,0,0);
        #pragma unroll
        for (int fq = 0; fq < 4; fq++) {
            float4 qb = shfl4(qv, qbase | fq);
            #pragma unroll
            for (int i = 0; i < 4; i++) {
                float4 a4 = *(const float4*)(A + (qd*4 + i)*16 + fq*4);
                float val = dot4(a4, qb);
                if (i == 0) qA.x += val;
                else if (i == 1) qA.y += val;
                else if (i == 2) qA.z += val;
                else qA.w += val;
            }
        }
        float pr = prel[t*Hh + hh] * 0.25f;

        float4 aggv = make_float4(0,0,0,0);
        float s = 0.f;
        int i0 = t*Nn + n, st = off[i0], dg = deg[i0];
        for (int j0 = 0; j0 < dg; j0 += 32) {
            int myS = (j0 + lane < dg) ? csr[st + j0 + lane] : 0;
            int cnt = min(32, dg - j0);
            for (int j = 0; j < cnt; j += 4) {
                int s0 = __shfl_sync(~0u, myS, j);
                int s1 = __shfl_sync(~0u, myS, (j+1) & 31);
                int s2 = __shfl_sync(~0u, myS, (j+2) & 31);
                int s3 = __shfl_sync(~0u, myS, (j+3) & 31);
                float4 k0 = *(const float4*)(k + (size_t)s0*Dd + lane*4);
                float4 k1 = *(const float4*)(k + (size_t)s1*Dd + lane*4);
                float4 k2 = *(const float4*)(k + (size_t)s2*Dd + lane*4);
                float4 k3 = *(const float4*)(k + (size_t)s3*Dd + lane*4);
                float4 v0 = *(const float4*)(v + (size_t)s0*Dd + lane*4);
                float4 v1 = *(const float4*)(v + (size_t)s1*Dd + lane*4);
                float4 v2 = *(const float4*)(v + (size_t)s2*Dd + lane*4);
                float4 v3 = *(const float4*)(v + (size_t)s3*Dd + lane*4);
                float pt0 = dot4(k0, qA);
                float pt1 = dot4(k1, qA);
                float pt2 = dot4(k2, qA);
                float pt3 = dot4(k3, qA);
                pt0 += __shfl_xor_sync(~0u, pt0, 1); pt0 += __shfl_xor_sync(~0u, pt0, 2);
                pt1 += __shfl_xor_sync(~0u, pt1, 1); pt1 += __shfl_xor_sync(~0u, pt1, 2);
                pt2 += __shfl_xor_sync(~0u, pt2, 1); pt2 += __shfl_xor_sync(~0u, pt2, 2);
                pt3 += __shfl_xor_sync(~0u, pt3, 1); pt3 += __shfl_xor_sync(~0u, pt3, 2);
                float p0 = expf(pt0 * pr);
                float p1 = (j+1 < cnt) ? expf(pt1 * pr) : 0.f;
                float p2 = (j+2 < cnt) ? expf(pt2 * pr) : 0.f;
                float p3 = (j+3 < cnt) ? expf(pt3 * pr) : 0.f;
                s += p0 + p1 + p2 + p3;
                aggv.x += v0.x*p0 + v1.x*p1 + v2.x*p2 + v3.x*p3;
                aggv.y += v0.y*p0 + v1.y*p1 + v2.y*p2 + v3.y*p3;
                aggv.z += v0.z*p0 + v1.z*p1 + v2.z*p2 + v3.z*p3;
                aggv.w += v0.w*p0 + v1.w*p1 + v2.w*p2 + v3.w*p3;
            }
        }
        const float* M = mrel + (size_t)((t*Hh + hh)*16)*16;
        float4 acc = make_float4(0,0,0,0);
        #pragma unroll
        for (int dq = 0; dq < 4; dq++) {
            float4 ab = shfl4(aggv, qbase | dq);
            float av[4] = {ab.x, ab.y, ab.z, ab.w};
            #pragma unroll
            for (int j = 0; j < 4; j++) {
                float4 m4 = *(const float4*)(M + (dq*4 + j)*16 + qd*4);
                float aj = av[j];
                acc.x += aj*m4.x; acc.y += aj*m4.y; acc.z += aj*m4.z; acc.w += aj*m4.w;
            }
        }
        *(float4*)(&smacc[t][lane*4]) = acc;
        if (qd == 0) sms[t][hh] = s;
    }
    __syncthreads();

    int d = tid;
    int dh = d >> 4;
    float a = smacc[0][d] + smacc[1][d] + smacc[2][d] + smacc[3][d];
    float stot = sms[0][dh] + sms[1][dh] + sms[2][dh] + sms[3][dh];
    float inv = 1.f / (stot > 0.f ? stot : 1.f);
    out[(size_t)n*Dd + d] = geluf(a * inv);
}

// ---------------- host launch ----------------
extern "C" void kernel_launch(void* const* d_in, const int* in_sizes, int n_in,
                              void* d_out, int out_size) {
    const float* zL  = (const float*)d_in[0];
    const float* zH  = (const float*)d_in[1];
    const float* xe  = (const float*)d_in[2];
    const float* W1  = (const float*)d_in[3];
    const float* as1 = (const float*)d_in[4];
    const float* ad1 = (const float*)d_in[5];
    const float* b1  = (const float*)d_in[6];
    const float* W2  = (const float*)d_in[7];
    const float* as2 = (const float*)d_in[8];
    const float* ad2 = (const float*)d_in[9];
    const float* b2  = (const float*)d_in[10];
    const float* Wk  = (const float*)d_in[11];
    const float* bk  = (const float*)d_in[12];
    const float* Wq  = (const float*)d_in[13];
    const float* bq  = (const float*)d_in[14];
    const float* Wv  = (const float*)d_in[15];
    const float* bv  = (const float*)d_in[16];
    const float* arel= (const float*)d_in[17];
    const float* mrel= (const float*)d_in[18];
    const float* prel= (const float*)d_in[19];
    const float* Wo  = (const float*)d_in[20];
    const float* bo  = (const float*)d_in[21];
    const float* skip= (const float*)d_in[22];
    const float* g1  = (const float*)d_in[23];
    const float* g2  = (const float*)d_in[24];
    const float* g3  = (const float*)d_in[25];
    const int* ei[4] = {(const int*)d_in[26], (const int*)d_in[27],
                        (const int*)d_in[28], (const int*)d_in[29]};

    float *h_, *k_, *q_, *v_, *tmp_, *al_, *ar_, *xw_;
    int *deg_, *off_, *cur_, *csr_, *bsum_;
    cudaGetSymbolAddress((void**)&h_,   g_h);
    cudaGetSymbolAddress((void**)&k_,   g_k);
    cudaGetSymbolAddress((void**)&q_,   g_q);
    cudaGetSymbolAddress((void**)&v_,   g_v);
    cudaGetSymbolAddress((void**)&tmp_, g_tmp);
    cudaGetSymbolAddress((void**)&al_,  g_al);
    cudaGetSymbolAddress((void**)&ar_,  g_ar);
    cudaGetSymbolAddress((void**)&xw_,  g_xw);
    cudaGetSymbolAddress((void**)&deg_, g_deg);
    cudaGetSymbolAddress((void**)&off_, g_off);
    cudaGetSymbolAddress((void**)&cur_, g_cur);
    cudaGetSymbolAddress((void**)&csr_, g_csr);
    cudaGetSymbolAddress((void**)&bsum_,g_bsum);

    const int nd = Nn*Dd;
    const int TPB = 256;
    const int gemm_grid = (Nn + 127) / 128;

    GemmArgs ga = {};
    ga.M = Nn;

    // Launch order: gemm_wm<1> is launch #4 (ncu captures #4).
    zeroint<<<(TN + TPB-1)/TPB, TPB>>>(deg_, TN);                                   // 1
    deg_k<<<(E4 + TPB-1)/TPB, TPB>>>(ei[0], ei[1], ei[2], ei[3], deg_);             // 2
    add3k<<<(nd/4 + TPB-1)/TPB, TPB>>>((const float4*)zL, (const float4*)zH,
                                       (const float4*)xe, (float4*)h_, nd/4);       // 3
    // GAT layer 1 GEMM (4 types)
    ga.A = h_;
    for (int t = 0; t < 4; t++) { ga.W[t] = W1 + (size_t)t*Dd*Dd; ga.bias[t] = nullptr;
                                  ga.C[t] = xw_ + (size_t)t*Nn*Dd; }
    ga.asb = as1; ga.adb = ad1; ga.al = al_; ga.ar = ar_;
    gemm_wm<1><<<dim3(gemm_grid, 4), 256>>>(ga);                                    // 4 (profiled)
    scan_pre<<<SCAN_NB, 1024>>>(deg_, bsum_);                                       // 5
    scan_mid<<<1, 256>>>(bsum_);                                                    // 6
    scan_post<<<SCAN_NB, 1024>>>(deg_, bsum_, off_, cur_);                          // 7
    fill_k<<<(E4 + TPB-1)/TPB, TPB>>>(ei[0], ei[1], ei[2], ei[3], cur_, csr_);      // 8

    gat_gather_b<<<Nn, 128>>>(csr_, off_, deg_, al_, ar_, xw_, b1, g1, h_);         // 9

    // GAT layer 2
    for (int t = 0; t < 4; t++) ga.W[t] = W2 + (size_t)t*Dd*Dd;
    ga.asb = as2; ga.adb = ad2;
    gemm_wm<1><<<dim3(gemm_grid, 4), 256>>>(ga);                                    // 10
    gat_gather_b<<<Nn, 128>>>(csr_, off_, deg_, al_, ar_, xw_, b2, g2, h_);         // 11

    // HGT: fused kqv
    GemmArgs gk = {};
    gk.M = Nn; gk.A = h_;
    gk.W[0] = Wk; gk.bias[0] = bk; gk.C[0] = k_;
    gk.W[1] = Wq; gk.bias[1] = bq; gk.C[1] = q_;
    gk.W[2] = Wv; gk.bias[2] = bv; gk.C[2] = v_;
    gemm_wm<0><<<dim3(gemm_grid, 3), 256>>>(gk);                                    // 12
    hgt_gather_b<<<Nn, 128>>>(csr_, off_, deg_, k_, q_, v_, arel, mrel, prel, tmp_);// 13

    GemmArgs gw = {};
    gw.M = Nn; gw.A = tmp_;
    gw.W[0] = Wo; gw.bias[0] = bo; gw.C[0] = nullptr;
    gw.hres = h_; gw.g = g3; gw.skip = skip; gw.out = (float*)d_out;
    gemm_wm<2><<<dim3(gemm_grid, 1), 256>>>(gw);                                    // 14
}